// round 2
// baseline (speedup 1.0000x reference)
#include <cuda_runtime.h>

#define NGRAPH 64
#define SPTS   1024
#define HIDDEN 256
#define NBLK   16          // blocks per graph: 12 full + 4 triangle
#define HISTW  (66*64)     // u32 words of shared histogram (66 rows x 256B)

typedef unsigned long long ull;

// cross-block partials + arrival counters (zero-initialized; counters self-reset)
__device__ unsigned int g_part[NGRAPH][NBLK][64];
__device__ unsigned int g_cnt[NGRAPH];

// ---------- helpers ----------
__device__ __forceinline__ unsigned smem_u32(const void* p) {
    unsigned a;
    asm("{ .reg .u64 t; cvta.to.shared.u64 t, %1; cvt.u32.u64 %0, t; }" : "=r"(a) : "l"(p));
    return a;
}
__device__ __forceinline__ ull f2_pack(float a, float b) {
    ull r; asm("mov.b64 %0, {%1, %2};" : "=l"(r) : "f"(a), "f"(b)); return r;
}
__device__ __forceinline__ void f2_unpack(ull v, float& a, float& b) {
    asm("mov.b64 {%0, %1}, %2;" : "=f"(a), "=f"(b) : "l"(v));
}
__device__ __forceinline__ ull f2_add(ull a, ull b) {
    ull r; asm("add.rn.f32x2 %0, %1, %2;" : "=l"(r) : "l"(a), "l"(b)); return r;
}
__device__ __forceinline__ ull f2_mul(ull a, ull b) {
    ull r; asm("mul.rn.f32x2 %0, %1, %2;" : "=l"(r) : "l"(a), "l"(b)); return r;
}
__device__ __forceinline__ ull f2_fma(ull a, ull b, ull c) {
    ull r; asm("fma.rn.f32x2 %0, %1, %2, %3;" : "=l"(r) : "l"(a), "l"(b), "l"(c)); return r;
}

// bin + bump: d2 is scaled squared distance; bins 0..63 valid, 64 = dump.
// v = bits(min(sqrt(d2),64) + (2^23-0.5)) = 0x4B000000 + k ; 0x4B000000*256 wraps to 0,
// so addr = v*256 + hbase lands on row k (256B/row) at this thread's private u16 slot.
__device__ __forceinline__ void hist_bump(float d2, unsigned hbase) {
    float d; asm("sqrt.approx.f32 %0, %1;" : "=f"(d) : "f"(d2));
    unsigned v = __float_as_uint(fminf(d, 64.0f) + 8388607.5f);
    unsigned addr = v * 256u + hbase;
    unsigned short c;
    asm volatile("ld.shared.u16 %0, [%1];" : "=h"(c) : "r"(addr));
    c = (unsigned short)(c + 1);
    asm volatile("st.shared.u16 [%0], %1;" :: "r"(addr), "h"(c));
}

// ---------- the one fused kernel ----------
// grid = (16, 64), block = 128.
//   m < 12 : full block — 256-row band r vs 128-col tile c (tile strictly after band)
//   m >= 12: triangle block — all i<j pairs inside 256-point band (m-12), zero waste
__global__ __launch_bounds__(128, 8) void fused_kernel(
    const float* __restrict__ pos,
    const float* __restrict__ W1, const float* __restrict__ b1,
    const float* __restrict__ W2, const float* __restrict__ b2,
    float* __restrict__ out)
{
    __shared__ unsigned int sh_hist[HISTW];                    // 16896 B
    __shared__ __align__(16) float xs[256], ys[256], zs[256];  // 3072 B
    __shared__ unsigned int red_u[128];
    __shared__ float hn_s[64];
    __shared__ float act[HIDDEN];
    __shared__ float inv_s;
    __shared__ int   flag_s;

    const int t = threadIdx.x;
    const int m = blockIdx.x;
    const int g = blockIdx.y;
    const float SCALE = 2.56f;   // NUM_BINS / MAX_DIST

    // zero private hist (u16[66 rows][128 slots] viewed as u32)
    #pragma unroll
    for (int i = t; i < HISTW; i += 128) sh_hist[i] = 0;

    // private u16 slot base: even lanes at 2t, odd lanes at 2t+64 -> 32 distinct banks
    const unsigned hbase = smem_u32(sh_hist) + 2u * (unsigned)t + ((t & 1) ? 64u : 0u);

    const float* gp = pos + (size_t)g * SPTS * 3;

    if (m < 12) {
        // ---- full block ----
        const int r = (m < 6) ? 0 : ((m < 10) ? 1 : 2);
        const int c = (m < 6) ? (m + 2) : ((m < 10) ? (m - 2) : (m - 4));
        {
            const float* q = gp + (size_t)(c * 128 + t) * 3;
            xs[t] = q[0] * SCALE; ys[t] = q[1] * SCALE; zs[t] = q[2] * SCALE;
        }
        const float* r0 = gp + (size_t)(r * 256 + t) * 3;
        const float* r1 = gp + (size_t)(r * 256 + 128 + t) * 3;
        const float x0 = r0[0] * SCALE, y0 = r0[1] * SCALE, z0 = r0[2] * SCALE;
        const float x1 = r1[0] * SCALE, y1 = r1[1] * SCALE, z1 = r1[2] * SCALE;
        const ull nx0 = f2_pack(-x0, -x0), ny0 = f2_pack(-y0, -y0), nz0 = f2_pack(-z0, -z0);
        const ull nx1 = f2_pack(-x1, -x1), ny1 = f2_pack(-y1, -y1), nz1 = f2_pack(-z1, -z1);
        __syncthreads();

        const ull* X2 = (const ull*)xs;
        const ull* Y2 = (const ull*)ys;
        const ull* Z2 = (const ull*)zs;

        #pragma unroll 4
        for (int h = 0; h < 64; ++h) {
            const ull X = X2[h], Y = Y2[h], Z = Z2[h];   // uniform broadcast loads
            {
                ull dx = f2_add(X, nx0), dy = f2_add(Y, ny0), dz = f2_add(Z, nz0);
                ull d2 = f2_fma(dx, dx, f2_fma(dy, dy, f2_mul(dz, dz)));
                float a, b; f2_unpack(d2, a, b);
                hist_bump(a, hbase); hist_bump(b, hbase);
            }
            {
                ull dx = f2_add(X, nx1), dy = f2_add(Y, ny1), dz = f2_add(Z, nz1);
                ull d2 = f2_fma(dx, dx, f2_fma(dy, dy, f2_mul(dz, dz)));
                float a, b; f2_unpack(d2, a, b);
                hist_bump(a, hbase); hist_bump(b, hbase);
            }
        }
    } else {
        // ---- triangle block over 256-point band ----
        const int band = m - 12;
        {
            const float* q  = gp + (size_t)(band * 256 + t) * 3;
            const float* q2 = gp + (size_t)(band * 256 + 128 + t) * 3;
            xs[t]       = q[0]  * SCALE; ys[t]       = q[1]  * SCALE; zs[t]       = q[2]  * SCALE;
            xs[128 + t] = q2[0] * SCALE; ys[128 + t] = q2[1] * SCALE; zs[128 + t] = q2[2] * SCALE;
        }
        __syncthreads();
        // thread t owns rows t and 255-t: constant 255 pairs/thread
        const float ax = xs[t],       ay = ys[t],       az = zs[t];
        const float bx = xs[255 - t], by = ys[255 - t], bz = zs[255 - t];
        for (int j = t + 1; j < 256; ++j) {
            float dx = xs[j] - ax, dy = ys[j] - ay, dz = zs[j] - az;
            hist_bump(fmaf(dx, dx, fmaf(dy, dy, dz * dz)), hbase);
        }
        for (int j = 256 - t; j < 256; ++j) {
            float dx = xs[j] - bx, dy = ys[j] - by, dz = zs[j] - bz;
            hist_bump(fmaf(dx, dx, fmaf(dy, dy, dz * dz)), hbase);
        }
    }
    __syncthreads();

    // ---- reduce 128 private u16 hists -> 64 bins (staggered, conflict-free) ----
    {
        unsigned s = 0;
        if (t < 64) {
            const int b = t;
            #pragma unroll 8
            for (int a = 0; a < 64; ++a) {
                int idx = (a + b) & 63;
                s += sh_hist[b * 64 + idx] & 0xFFFFu;          // even-lane slots (low half)
            }
        } else {
            const int b = t - 64;
            #pragma unroll 8
            for (int a = 0; a < 64; ++a) {
                int idx = (a + b) & 63;
                s += sh_hist[b * 64 + 16 + idx] >> 16;         // odd-lane slots (high half)
            }
        }
        red_u[t] = s;
    }
    __syncthreads();
    if (t < 64) g_part[g][m][t] = red_u[t] + red_u[t + 64];
    __threadfence();
    __syncthreads();

    if (t == 0) {
        unsigned old = atomicAdd(&g_cnt[g], 1u);
        flag_s = (old == NBLK - 1) ? 1 : 0;
    }
    __syncthreads();
    if (!flag_s) return;

    // ---- last block of this graph: reduce partials, normalize, MLP ----
    __threadfence();   // acquire
    if (t < 64) {
        unsigned s = 0;
        #pragma unroll
        for (int mm = 0; mm < NBLK; ++mm) s += __ldcg(&g_part[g][mm][t]);
        hn_s[t] = (float)s;
    }
    __syncthreads();
    if (t == 0) {
        float ts = 0.0f;
        #pragma unroll
        for (int k = 0; k < 64; ++k) ts += hn_s[k];
        inv_s = 1.0f / (ts + 1e-8f);
        g_cnt[g] = 0;                        // self-reset for next launch
    }
    __syncthreads();
    const float inv = inv_s;

    // layer 1: silu(hist @ W1.T + b1), two units per thread
    #pragma unroll
    for (int u = t; u < HIDDEN; u += 128) {
        const float4* w = reinterpret_cast<const float4*>(W1 + (size_t)u * 64);
        float dot = 0.0f;
        #pragma unroll
        for (int k = 0; k < 16; ++k) {
            float4 ww = w[k];
            dot = fmaf(ww.x, hn_s[4*k+0], dot);
            dot = fmaf(ww.y, hn_s[4*k+1], dot);
            dot = fmaf(ww.z, hn_s[4*k+2], dot);
            dot = fmaf(ww.w, hn_s[4*k+3], dot);
        }
        float x  = fmaf(dot, inv, b1[u]);
        float sg = 1.0f / (1.0f + __expf(-x));
        act[u] = x * sg;
    }
    __syncthreads();

    // layer 2: h @ W2.T + b2
    #pragma unroll
    for (int u = t; u < HIDDEN; u += 128) {
        const float4* w = reinterpret_cast<const float4*>(W2 + (size_t)u * HIDDEN);
        float acc = b2[u];
        #pragma unroll 8
        for (int k = 0; k < 64; ++k) {
            float4 ww = w[k];
            acc = fmaf(ww.x, act[4*k+0], acc);
            acc = fmaf(ww.y, act[4*k+1], acc);
            acc = fmaf(ww.z, act[4*k+2], acc);
            acc = fmaf(ww.w, act[4*k+3], acc);
        }
        out[(size_t)g * HIDDEN + u] = acc;
    }
}

extern "C" void kernel_launch(void* const* d_in, const int* in_sizes, int n_in,
                              void* d_out, int out_size) {
    // metadata order: pos, W1, b1, W2, b2, batch. Size-based ID; first 65536 = W2
    // (batch, also 65536 elems, comes last).
    int iPos = 0, iW1 = 1, ib1 = 2, iW2 = 3, ib2 = 4;
    {
        int fp = -1, f1 = -1, f2v = -1, fb1 = -1, fb2 = -1;
        for (int i = 0; i < n_in; ++i) {
            int s = in_sizes[i];
            if (s == 196608 && fp < 0) fp = i;
            else if (s == 16384 && f1 < 0) f1 = i;
            else if (s == 65536 && f2v < 0) f2v = i;
            else if (s == 256) { if (fb1 < 0) fb1 = i; else if (fb2 < 0) fb2 = i; }
        }
        if (fp >= 0 && f1 >= 0 && f2v >= 0 && fb1 >= 0 && fb2 >= 0) {
            iPos = fp; iW1 = f1; iW2 = f2v; ib1 = fb1; ib2 = fb2;
        }
    }
    const float* pos = (const float*)d_in[iPos];
    const float* W1  = (const float*)d_in[iW1];
    const float* b1  = (const float*)d_in[ib1];
    const float* W2  = (const float*)d_in[iW2];
    const float* b2  = (const float*)d_in[ib2];
    float* out = (float*)d_out;

    fused_kernel<<<dim3(NBLK, NGRAPH), 128>>>(pos, W1, b1, W2, b2, out);
}

// round 4
// speedup vs baseline: 1.6772x; 1.6772x over previous
#include <cuda_runtime.h>

#define NGRAPH 64
#define SPTS   1024
#define TILE   128
#define NTILE  8
#define NPAIRS 36           // tile-pairs per graph (ti <= tj)
#define HIDDEN 256
#define NBINS  64
#define HROWS  65           // 64 bins + dump row

typedef unsigned long long ull;

// per-(graph, tile-pair-block) partial histograms; fully overwritten every call
__device__ unsigned int g_part[NGRAPH][NPAIRS][NBINS];

// ---------- f32x2 packed helpers ----------
__device__ __forceinline__ ull f2_pack(float a, float b) {
    ull r; asm("mov.b64 %0, {%1, %2};" : "=l"(r) : "f"(a), "f"(b)); return r;
}
__device__ __forceinline__ void f2_unpack(ull v, float& a, float& b) {
    asm("mov.b64 {%0, %1}, %2;" : "=f"(a), "=f"(b) : "l"(v));
}
__device__ __forceinline__ ull f2_add(ull a, ull b) {
    ull r; asm("add.rn.f32x2 %0, %1, %2;" : "=l"(r) : "l"(a), "l"(b)); return r;
}
__device__ __forceinline__ ull f2_mul(ull a, ull b) {
    ull r; asm("mul.rn.f32x2 %0, %1, %2;" : "=l"(r) : "l"(a), "l"(b)); return r;
}
__device__ __forceinline__ ull f2_fma(ull a, ull b, ull c) {
    ull r; asm("fma.rn.f32x2 %0, %1, %2, %3;" : "=l"(r) : "l"(a), "l"(b), "l"(c)); return r;
}
__device__ __forceinline__ float fsqrt_approx(float x) {
    float y; asm("sqrt.approx.f32 %0, %1;" : "=f"(y) : "f"(x)); return y;
}

// bin index: scaled distance d in [0,inf) -> k in [0,64]; 64 = dump row.
// bits(fmin(d,64) + (2^23-0.5)) = 0x4B000000 + floor(min(d,64)) in the common
// case; for d in (0,0.25) the FADD rounds DOWN to 0x4AFFFFFF, so clamp the
// signed difference at 0 (those pairs belong in bin 0). Upper side already
// clamped by fminf -> k <= 64. Always in-bounds.
__device__ __forceinline__ unsigned bin_of(float d2) {
    float d = fsqrt_approx(d2);
    unsigned v = __float_as_uint(fminf(d, 64.0f) + 8388607.5f);
    int k = (int)v - 0x4B000000;
    return (unsigned)max(k, 0);
}

// ---------- kernel 1: pairwise histogram ----------
// grid = (36 tile-pairs, 64 graphs), block = 128 threads.
// Thread t owns row i=t of the row tile, sweeps 128 columns (2 per f32x2 step).
// Counts go to per-THREAD private u32 hist[k][t]: bank = t%32, conflict-free.
__global__ __launch_bounds__(TILE) void hist_kernel(const float* __restrict__ pos) {
    __shared__ unsigned int sh_hist[HROWS * TILE];        // 33280 B
    __shared__ __align__(16) float xs[TILE], ys[TILE], zs[TILE];
    __shared__ unsigned int red_u[TILE];

    const int t = threadIdx.x;
    const int g = blockIdx.y;

    // map blockIdx.x -> (ti, tj), ti <= tj
    int ti = 0, rem = blockIdx.x;
    while (rem >= NTILE - ti) { rem -= NTILE - ti; ++ti; }
    const int tj = ti + rem;

    #pragma unroll
    for (int r = 0; r < HROWS; ++r) sh_hist[r * TILE + t] = 0;

    const float SCALE = 2.56f;   // NUM_BINS / MAX_DIST

    {
        const float* q = pos + ((size_t)(g * SPTS + tj * TILE + t)) * 3;
        xs[t] = q[0] * SCALE; ys[t] = q[1] * SCALE; zs[t] = q[2] * SCALE;
    }
    const float* r = pos + ((size_t)(g * SPTS + ti * TILE + t)) * 3;
    const float xi = r[0] * SCALE, yi = r[1] * SCALE, zi = r[2] * SCALE;
    const ull nxi = f2_pack(-xi, -xi);
    const ull nyi = f2_pack(-yi, -yi);
    const ull nzi = f2_pack(-zi, -zi);

    __syncthreads();

    const ull* X2 = (const ull*)xs;
    const ull* Y2 = (const ull*)ys;
    const ull* Z2 = (const ull*)zs;
    unsigned int* myhist = sh_hist + t;

    if (ti != tj) {
        // off-diagonal: every slot is a valid pair — no predicate
        #pragma unroll 4
        for (int h = 0; h < TILE / 2; ++h) {
            ull dx = f2_add(X2[h], nxi);
            ull dy = f2_add(Y2[h], nyi);
            ull dz = f2_add(Z2[h], nzi);
            ull d2 = f2_fma(dx, dx, f2_fma(dy, dy, f2_mul(dz, dz)));
            float a, b; f2_unpack(d2, a, b);
            myhist[bin_of(a) * TILE] += 1u;
            myhist[bin_of(b) * TILE] += 1u;
        }
    } else {
        // diagonal: count only j > i (i = t)
        #pragma unroll 4
        for (int h = 0; h < TILE / 2; ++h) {
            const int j0 = 2 * h;
            ull dx = f2_add(X2[h], nxi);
            ull dy = f2_add(Y2[h], nyi);
            ull dz = f2_add(Z2[h], nzi);
            ull d2 = f2_fma(dx, dx, f2_fma(dy, dy, f2_mul(dz, dz)));
            float a, b; f2_unpack(d2, a, b);
            myhist[bin_of(a) * TILE] += (j0 > t) ? 1u : 0u;
            myhist[bin_of(b) * TILE] += (j0 + 1 > t) ? 1u : 0u;
        }
    }

    __syncthreads();

    // reduce 128 private hists -> 64 bins (rotated, bank-conflict-free)
    {
        const int b   = t & 63;
        const int seg = t >> 6;
        unsigned s = 0;
        #pragma unroll 8
        for (int a = 0; a < 64; ++a) {
            int col = seg * 64 + ((a + b) & 63);
            s += sh_hist[b * TILE + col];
        }
        red_u[t] = s;
    }
    __syncthreads();
    if (t < NBINS) g_part[g][blockIdx.x][t] = red_u[t] + red_u[t + 64];
}

// ---------- kernel 2: sum partials + normalize + MLP ----------
// grid = 64 graphs, block = 256 threads (one per hidden / output unit)
__global__ __launch_bounds__(HIDDEN) void mlp_kernel(const float* __restrict__ W1,
                                                     const float* __restrict__ b1,
                                                     const float* __restrict__ W2,
                                                     const float* __restrict__ b2,
                                                     float* __restrict__ out) {
    const int g = blockIdx.x;
    const int t = threadIdx.x;
    __shared__ float hn[NBINS];
    __shared__ float h[HIDDEN];
    __shared__ float inv_s;

    if (t < NBINS) {
        unsigned s = 0;
        #pragma unroll
        for (int m = 0; m < NPAIRS; ++m) s += g_part[g][m][t];
        hn[t] = (float)s;
    }
    __syncthreads();
    if (t == 0) {
        float s = 0.0f;
        #pragma unroll
        for (int k = 0; k < NBINS; ++k) s += hn[k];
        inv_s = 1.0f / (s + 1e-8f);
    }
    __syncthreads();
    const float inv = inv_s;

    // layer 1: silu(hist_norm @ W1.T + b1)
    float dot = 0.0f;
    const float4* w1r = reinterpret_cast<const float4*>(W1 + (size_t)t * NBINS);
    #pragma unroll
    for (int k = 0; k < NBINS / 4; ++k) {
        float4 w = w1r[k];
        dot = fmaf(w.x, hn[4*k+0], dot);
        dot = fmaf(w.y, hn[4*k+1], dot);
        dot = fmaf(w.z, hn[4*k+2], dot);
        dot = fmaf(w.w, hn[4*k+3], dot);
    }
    float x   = fmaf(dot, inv, b1[t]);
    float sig = 1.0f / (1.0f + __expf(-x));
    h[t] = x * sig;
    __syncthreads();

    // layer 2
    float acc = b2[t];
    const float4* w2r = reinterpret_cast<const float4*>(W2 + (size_t)t * HIDDEN);
    #pragma unroll 8
    for (int k = 0; k < HIDDEN / 4; ++k) {
        float4 w = w2r[k];
        acc = fmaf(w.x, h[4*k+0], acc);
        acc = fmaf(w.y, h[4*k+1], acc);
        acc = fmaf(w.z, h[4*k+2], acc);
        acc = fmaf(w.w, h[4*k+3], acc);
    }
    out[(size_t)g * HIDDEN + t] = acc;
}

extern "C" void kernel_launch(void* const* d_in, const int* in_sizes, int n_in,
                              void* d_out, int out_size) {
    // Size-based input ID: pos=196608, W1=16384, W2=first 65536 (batch i32 comes
    // later), b1/b2 = 256 in order.
    int iPos = 0, iW1 = 1, ib1 = 2, iW2 = 3, ib2 = 4;
    {
        int fp = -1, f1 = -1, f2v = -1, fb1 = -1, fb2 = -1;
        for (int i = 0; i < n_in; ++i) {
            int s = in_sizes[i];
            if (s == 196608 && fp < 0) fp = i;
            else if (s == 16384 && f1 < 0) f1 = i;
            else if (s == 65536 && f2v < 0) f2v = i;
            else if (s == 256) { if (fb1 < 0) fb1 = i; else if (fb2 < 0) fb2 = i; }
        }
        if (fp >= 0 && f1 >= 0 && f2v >= 0 && fb1 >= 0 && fb2 >= 0) {
            iPos = fp; iW1 = f1; iW2 = f2v; ib1 = fb1; ib2 = fb2;
        }
    }
    const float* pos = (const float*)d_in[iPos];
    const float* W1  = (const float*)d_in[iW1];
    const float* b1  = (const float*)d_in[ib1];
    const float* W2  = (const float*)d_in[iW2];
    const float* b2  = (const float*)d_in[ib2];
    float* out = (float*)d_out;

    hist_kernel<<<dim3(NPAIRS, NGRAPH), TILE>>>(pos);
    mlp_kernel<<<NGRAPH, HIDDEN>>>(W1, b1, W2, b2, out);
}

// round 5
// speedup vs baseline: 1.7513x; 1.0442x over previous
#include <cuda_runtime.h>

#define NGRAPH 64
#define SPTS   1024
#define TILE   128
#define NTILE  8
#define NPAIRS 36           // tile-pairs per graph (ti <= tj)
#define HIDDEN 256
#define NBINS  64
#define HROWS  65           // 64 bins + dump row

typedef unsigned long long ull;

// per-(graph, tile-pair-block) partial histograms; fully overwritten every call
__device__ unsigned int g_part[NGRAPH][NPAIRS][NBINS];

// ---------- f32x2 packed helpers ----------
__device__ __forceinline__ ull f2_pack(float a, float b) {
    ull r; asm("mov.b64 %0, {%1, %2};" : "=l"(r) : "f"(a), "f"(b)); return r;
}
__device__ __forceinline__ void f2_unpack(ull v, float& a, float& b) {
    asm("mov.b64 {%0, %1}, %2;" : "=f"(a), "=f"(b) : "l"(v));
}
__device__ __forceinline__ ull f2_add(ull a, ull b) {
    ull r; asm("add.rn.f32x2 %0, %1, %2;" : "=l"(r) : "l"(a), "l"(b)); return r;
}
__device__ __forceinline__ ull f2_mul(ull a, ull b) {
    ull r; asm("mul.rn.f32x2 %0, %1, %2;" : "=l"(r) : "l"(a), "l"(b)); return r;
}
__device__ __forceinline__ ull f2_fma(ull a, ull b, ull c) {
    ull r; asm("fma.rn.f32x2 %0, %1, %2, %3;" : "=l"(r) : "l"(a), "l"(b), "l"(c)); return r;
}
__device__ __forceinline__ float fsqrt_approx(float x) {
    float y; asm("sqrt.approx.f32 %0, %1;" : "=f"(y) : "f"(x)); return y;
}

// bin index: scaled distance d in [0,inf) -> k in [0,64]; 64 = dump row.
// bits(fmin(d,64) + (2^23-0.5)) = 0x4B000000 + floor(min(d,64)) in the common
// case; for d in (0,0.25) the FADD rounds DOWN to 0x4AFFFFFF, so clamp the
// signed difference at 0 (those pairs belong in bin 0). Always in-bounds.
__device__ __forceinline__ unsigned bin_of(float d2) {
    float d = fsqrt_approx(d2);
    unsigned v = __float_as_uint(fminf(d, 64.0f) + 8388607.5f);
    int k = (int)v - 0x4B000000;
    return (unsigned)max(k, 0);
}

// ---------- kernel 1: pairwise histogram (unchanged, measured-good) ----------
__global__ __launch_bounds__(TILE) void hist_kernel(const float* __restrict__ pos) {
    __shared__ unsigned int sh_hist[HROWS * TILE];        // 33280 B
    __shared__ __align__(16) float xs[TILE], ys[TILE], zs[TILE];
    __shared__ unsigned int red_u[TILE];

    const int t = threadIdx.x;
    const int g = blockIdx.y;

    int ti = 0, rem = blockIdx.x;
    while (rem >= NTILE - ti) { rem -= NTILE - ti; ++ti; }
    const int tj = ti + rem;

    #pragma unroll
    for (int r = 0; r < HROWS; ++r) sh_hist[r * TILE + t] = 0;

    const float SCALE = 2.56f;   // NUM_BINS / MAX_DIST

    {
        const float* q = pos + ((size_t)(g * SPTS + tj * TILE + t)) * 3;
        xs[t] = q[0] * SCALE; ys[t] = q[1] * SCALE; zs[t] = q[2] * SCALE;
    }
    const float* r = pos + ((size_t)(g * SPTS + ti * TILE + t)) * 3;
    const float xi = r[0] * SCALE, yi = r[1] * SCALE, zi = r[2] * SCALE;
    const ull nxi = f2_pack(-xi, -xi);
    const ull nyi = f2_pack(-yi, -yi);
    const ull nzi = f2_pack(-zi, -zi);

    __syncthreads();

    const ull* X2 = (const ull*)xs;
    const ull* Y2 = (const ull*)ys;
    const ull* Z2 = (const ull*)zs;
    unsigned int* myhist = sh_hist + t;

    if (ti != tj) {
        #pragma unroll 4
        for (int h = 0; h < TILE / 2; ++h) {
            ull dx = f2_add(X2[h], nxi);
            ull dy = f2_add(Y2[h], nyi);
            ull dz = f2_add(Z2[h], nzi);
            ull d2 = f2_fma(dx, dx, f2_fma(dy, dy, f2_mul(dz, dz)));
            float a, b; f2_unpack(d2, a, b);
            myhist[bin_of(a) * TILE] += 1u;
            myhist[bin_of(b) * TILE] += 1u;
        }
    } else {
        #pragma unroll 4
        for (int h = 0; h < TILE / 2; ++h) {
            const int j0 = 2 * h;
            ull dx = f2_add(X2[h], nxi);
            ull dy = f2_add(Y2[h], nyi);
            ull dz = f2_add(Z2[h], nzi);
            ull d2 = f2_fma(dx, dx, f2_fma(dy, dy, f2_mul(dz, dz)));
            float a, b; f2_unpack(d2, a, b);
            myhist[bin_of(a) * TILE] += (j0 > t) ? 1u : 0u;
            myhist[bin_of(b) * TILE] += (j0 + 1 > t) ? 1u : 0u;
        }
    }

    __syncthreads();

    {
        const int b   = t & 63;
        const int seg = t >> 6;
        unsigned s = 0;
        #pragma unroll 8
        for (int a = 0; a < 64; ++a) {
            int col = seg * 64 + ((a + b) & 63);
            s += sh_hist[b * TILE + col];
        }
        red_u[t] = s;
    }
    __syncthreads();
    if (t < NBINS) g_part[g][blockIdx.x][t] = red_u[t] + red_u[t + 64];
}

// ---------- kernel 2: sum partials + normalize + MLP ----------
// grid = (4 unit-slices, 64 graphs), block = 128 threads.
// Each block redundantly does the cheap normalize + full layer-1 (W1 L2-hot),
// then layer-2 for its 64 output units with 2 threads per unit (K split in
// half, combined via shfl). 4x the blocks and 4x less W2 per block vs R4.
__global__ __launch_bounds__(128) void mlp_kernel(const float* __restrict__ W1,
                                                  const float* __restrict__ b1,
                                                  const float* __restrict__ W2,
                                                  const float* __restrict__ b2,
                                                  float* __restrict__ out) {
    const int g = blockIdx.y;
    const int s = blockIdx.x;      // unit slice 0..3
    const int t = threadIdx.x;

    __shared__ float hn[NBINS];
    __shared__ __align__(16) float act[HIDDEN];
    __shared__ float inv_s;

    if (t < NBINS) {
        unsigned sum = 0;
        #pragma unroll
        for (int m = 0; m < NPAIRS; ++m) sum += g_part[g][m][t];
        hn[t] = (float)sum;
    }
    __syncthreads();
    if (t == 0) {
        float ssum = 0.0f;
        #pragma unroll
        for (int k = 0; k < NBINS; ++k) ssum += hn[k];
        inv_s = 1.0f / (ssum + 1e-8f);
    }
    __syncthreads();
    const float inv = inv_s;

    // layer 1: silu(hist_norm @ W1.T + b1) -> act[256] (2 units per thread)
    #pragma unroll
    for (int u = t; u < HIDDEN; u += 128) {
        const float4* w = reinterpret_cast<const float4*>(W1 + (size_t)u * NBINS);
        float dot = 0.0f;
        #pragma unroll
        for (int k = 0; k < NBINS / 4; ++k) {
            float4 ww = w[k];
            dot = fmaf(ww.x, hn[4*k+0], dot);
            dot = fmaf(ww.y, hn[4*k+1], dot);
            dot = fmaf(ww.z, hn[4*k+2], dot);
            dot = fmaf(ww.w, hn[4*k+3], dot);
        }
        float x   = fmaf(dot, inv, b1[u]);
        float sig = 1.0f / (1.0f + __expf(-x));
        act[u] = x * sig;
    }
    __syncthreads();

    // layer 2: 64 units for this slice; 2 threads per unit, each half of K
    {
        const int u    = s * 64 + (t >> 1);
        const int half = t & 1;
        const float4* w = reinterpret_cast<const float4*>(W2 + (size_t)u * HIDDEN + half * 128);
        const float4* a = reinterpret_cast<const float4*>(act + half * 128);
        float acc = 0.0f;
        #pragma unroll 8
        for (int k = 0; k < 32; ++k) {
            float4 ww = w[k];
            float4 aa = a[k];
            acc = fmaf(ww.x, aa.x, acc);
            acc = fmaf(ww.y, aa.y, acc);
            acc = fmaf(ww.z, aa.z, acc);
            acc = fmaf(ww.w, aa.w, acc);
        }
        // combine the two halves deterministically: low-half value + high-half value
        float other = __shfl_xor_sync(0xffffffffu, acc, 1);
        if (half == 0)
            out[(size_t)g * HIDDEN + u] = (acc + other) + b2[u];
    }
}

extern "C" void kernel_launch(void* const* d_in, const int* in_sizes, int n_in,
                              void* d_out, int out_size) {
    // Size-based input ID: pos=196608, W1=16384, W2=first 65536 (batch i32 comes
    // later), b1/b2 = 256 in order.
    int iPos = 0, iW1 = 1, ib1 = 2, iW2 = 3, ib2 = 4;
    {
        int fp = -1, f1 = -1, f2v = -1, fb1 = -1, fb2 = -1;
        for (int i = 0; i < n_in; ++i) {
            int sz = in_sizes[i];
            if (sz == 196608 && fp < 0) fp = i;
            else if (sz == 16384 && f1 < 0) f1 = i;
            else if (sz == 65536 && f2v < 0) f2v = i;
            else if (sz == 256) { if (fb1 < 0) fb1 = i; else if (fb2 < 0) fb2 = i; }
        }
        if (fp >= 0 && f1 >= 0 && f2v >= 0 && fb1 >= 0 && fb2 >= 0) {
            iPos = fp; iW1 = f1; iW2 = f2v; ib1 = fb1; ib2 = fb2;
        }
    }
    const float* pos = (const float*)d_in[iPos];
    const float* W1  = (const float*)d_in[iW1];
    const float* b1  = (const float*)d_in[ib1];
    const float* W2  = (const float*)d_in[iW2];
    const float* b2  = (const float*)d_in[ib2];
    float* out = (float*)d_out;

    hist_kernel<<<dim3(NPAIRS, NGRAPH), TILE>>>(pos);
    mlp_kernel<<<dim3(4, NGRAPH), 128>>>(W1, b1, W2, b2, out);
}